// round 5
// baseline (speedup 1.0000x reference)
#include <cuda_runtime.h>
#include <math.h>
#include <stdint.h>
#include <stddef.h>

#define Bdim  64
#define Tdim  512
#define INdim 256
#define Hdim  512
#define G4    2048
#define NBLK  128
#define SHP   516   // padded pitch for h tile rows (floats); +16-word skew for rows >= 8

typedef unsigned long long ull;

// ---------------- packed f32x2 helpers ----------------
#define PK2(d, lo, hi) \
    asm("mov.b64 %0, {%1, %2};" : "=l"(d) : "f"(lo), "f"(hi))
#define UPK2(lo, hi, v) \
    asm("mov.b64 {%0, %1}, %2;" : "=f"(lo), "=f"(hi) : "l"(v))
#define FMA2(acc, a, b) \
    asm("fma.rn.f32x2 %0, %1, %2, %0;" : "+l"(acc) : "l"(a), "l"(b))

// ---------------- device-global scratch (no allocations allowed) ----------------
__device__ __align__(16) float g_G[(size_t)Bdim * Tdim * G4];     // input-gate precompute
__device__ __align__(16) float g_hs0[(size_t)Bdim * Tdim * Hdim]; // layer-0 hidden sequence
__device__ __align__(16) float g_bufA[Bdim * Hdim];               // double-buffered h state
__device__ __align__(16) float g_bufB[Bdim * Hdim];
__device__ __align__(16) float g_h0f[Bdim * Hdim];                // layer-0 final h
__device__ __align__(16) float g_c0f[Bdim * Hdim];                // layer-0 final c
__device__ unsigned g_arrive[NBLK];                               // per-CTA arrival flags
__device__ volatile unsigned g_release;                           // barrier release word

// ---------------- flag-array grid barrier (all NBLK CTAs resident) ----------------
// target values are strictly increasing within a launch; g_release is read once
// at kernel start to derive the base, so graph replays are safe.
__device__ __forceinline__ void grid_barrier(unsigned target) {
    __syncthreads();
    const int tid = threadIdx.x;
    if (tid == 0) {
        __threadfence();                                  // publish our global writes
        ((volatile unsigned*)g_arrive)[blockIdx.x] = target;
    }
    if (blockIdx.x == 0) {
        if (tid < NBLK) {
            while (((volatile unsigned*)g_arrive)[tid] != target) { }
        }
        __syncthreads();
        if (tid == 0) {
            __threadfence();
            g_release = target;
        }
    } else if (tid == 0) {
        while (g_release != target) { }
    }
    __syncthreads();
}

// ---------------- GEMM: C[m,n] = sum_k A[m,k]*Bw[n,k] + bias1[n] + bias2[n] ----------------
// A: [32768, K] row-major, Bw: [2048, K] row-major, C: [32768, 2048].
// BM=128, BN=64, BK=16, 256 threads, 8x4 register tile per thread; f32x2 packed
// math pairing adjacent output ROWS (a-pairs come free from the As vector load).
__global__ __launch_bounds__(256) void gemm_nt_bias(
    const float* __restrict__ A,
    const float* __restrict__ Bw,
    const float* __restrict__ bias1,
    const float* __restrict__ bias2,
    float* __restrict__ C,
    int K)
{
    __shared__ __align__(16) float As[16 * 132];
    __shared__ __align__(16) float Bs[16 * 68];
    const int tid = threadIdx.x;
    const int m0 = blockIdx.y * 128;
    const int n0 = blockIdx.x * 64;
    const int ty = tid >> 4;   // 0..15 -> 8 output rows each
    const int tx = tid & 15;   // 0..15 -> 4 output cols each

    ull acc2[4][4];            // [row-pair p][col j] = (row 2p, row 2p+1)
#pragma unroll
    for (int p = 0; p < 4; ++p)
#pragma unroll
        for (int j = 0; j < 4; ++j) acc2[p][j] = 0ull;

    for (int k0 = 0; k0 < K; k0 += 16) {
        // stage A tile transposed: As[k][m]
#pragma unroll
        for (int i = 0; i < 2; ++i) {
            int idx = i * 256 + tid;
            int row = idx >> 2, kq = idx & 3;
            float4 v = __ldg((const float4*)&A[(size_t)(m0 + row) * K + k0 + kq * 4]);
            As[(kq * 4 + 0) * 132 + row] = v.x;
            As[(kq * 4 + 1) * 132 + row] = v.y;
            As[(kq * 4 + 2) * 132 + row] = v.z;
            As[(kq * 4 + 3) * 132 + row] = v.w;
        }
        // stage B tile transposed: Bs[k][n]
        {
            int row = tid >> 2, kq = tid & 3;
            float4 v = __ldg((const float4*)&Bw[(size_t)(n0 + row) * K + k0 + kq * 4]);
            Bs[(kq * 4 + 0) * 68 + row] = v.x;
            Bs[(kq * 4 + 1) * 68 + row] = v.y;
            Bs[(kq * 4 + 2) * 68 + row] = v.z;
            Bs[(kq * 4 + 3) * 68 + row] = v.w;
        }
        __syncthreads();
#pragma unroll
        for (int kk = 0; kk < 16; ++kk) {
            // a row-pairs directly from vector loads (no packs)
            ulonglong2 av0 = *(const ulonglong2*)&As[kk * 132 + ty * 8];      // (r0,r1),(r2,r3)
            ulonglong2 av1 = *(const ulonglong2*)&As[kk * 132 + ty * 8 + 4];  // (r4,r5),(r6,r7)
            float4 bv = *(const float4*)&Bs[kk * 68 + tx * 4];
            ull bp0, bp1, bp2, bp3;
            PK2(bp0, bv.x, bv.x); PK2(bp1, bv.y, bv.y);
            PK2(bp2, bv.z, bv.z); PK2(bp3, bv.w, bv.w);
            ull ap[4] = {av0.x, av0.y, av1.x, av1.y};
#pragma unroll
            for (int p = 0; p < 4; ++p) {
                FMA2(acc2[p][0], ap[p], bp0);
                FMA2(acc2[p][1], ap[p], bp1);
                FMA2(acc2[p][2], ap[p], bp2);
                FMA2(acc2[p][3], ap[p], bp3);
            }
        }
        __syncthreads();
    }

    float4 b1 = __ldg((const float4*)&bias1[n0 + tx * 4]);
    float4 b2 = __ldg((const float4*)&bias2[n0 + tx * 4]);
    float bs[4] = {b1.x + b2.x, b1.y + b2.y, b1.z + b2.z, b1.w + b2.w};
#pragma unroll
    for (int p = 0; p < 4; ++p) {
        float lo[4], hi[4];
#pragma unroll
        for (int j = 0; j < 4; ++j) UPK2(lo[j], hi[j], acc2[p][j]);
        float4 o0 = make_float4(lo[0] + bs[0], lo[1] + bs[1], lo[2] + bs[2], lo[3] + bs[3]);
        float4 o1 = make_float4(hi[0] + bs[0], hi[1] + bs[1], hi[2] + bs[2], hi[3] + bs[3]);
        *(float4*)&C[(size_t)(m0 + ty * 8 + 2 * p + 0) * G4 + n0 + tx * 4] = o0;
        *(float4*)&C[(size_t)(m0 + ty * 8 + 2 * p + 1) * G4 + n0 + tx * 4] = o1;
    }
}

// ---------------- persistent LSTM recurrence ----------------
// 128 CTAs = 4 batch-tiles (16 b) x 32 unit-tiles (16 u). CTA computes its
// 16b x 64c (4 gates x 16 u) gate block each step; W_hh slice resident in smem.
// Dot phase: thread tile 8b x 4c, k-split 8; f32x2 pairing over k (both operands
// loaded as 64-bit pairs straight from smem). One flag-barrier per step.
__global__ __launch_bounds__(256, 1) void lstm_rec(
    const float* __restrict__ Whh,
    const int*   __restrict__ length,
    float*       __restrict__ hs_out,
    int layer)
{
    extern __shared__ float sm[];
    float* sWt   = sm;                    // [512][64]       transposed W slice
    float* sH    = sWt + 512 * 64;        // 16 rows, SHP pitch, +16 skew for b>=8
    float* sRed  = sH + (16 * SHP + 16);  // [8][16][64]     k-split partials
    float* sGate = sRed + 8 * 16 * 64;    // [16][68]        finished gates

    const int tid = threadIdx.x;
    const int ui = blockIdx.x & 31, bi = blockIdx.x >> 5;
    const int u0 = ui * 16, b0 = bi * 16;

    const unsigned gen0 = g_release;      // barrier base for this launch (replay-safe)

    // Load W_hh slice transposed: sWt[k*64 + c], local col c = gate*16 + lu.
    for (int i = tid; i < 64 * 128; i += 256) {
        int c = i & 63;
        int kq = i >> 6;  // 0..127
        int grow = (c >> 4) * Hdim + u0 + (c & 15);
        float4 v = __ldg((const float4*)&Whh[(size_t)grow * Hdim + kq * 4]);
        sWt[(kq * 4 + 0) * 64 + c] = v.x;
        sWt[(kq * 4 + 1) * 64 + c] = v.y;
        sWt[(kq * 4 + 2) * 64 + c] = v.z;
        sWt[(kq * 4 + 3) * 64 + c] = v.w;
    }

    // state-cell mapping: one thread per (batch, unit)
    const int ub = tid >> 4, lu = tid & 15;
    const int gb = b0 + ub;
    const int gu = u0 + lu;
    const int len = __ldg(&length[gb]);
    float h0f_r = 0.f, c0f_r = 0.f;
    if (layer) {
        h0f_r = g_h0f[gb * Hdim + gu];
        c0f_r = g_c0f[gb * Hdim + gu];
    }
    float h_reg = 0.f, c_reg = 0.f;
    g_bufA[gb * Hdim + gu] = 0.f;   // h(t=-1) = 0

    // dot-phase mapping: tid = ks*32 + bq*16 + cq  (warp-uniform ks)
    const int ks = tid >> 5;          // K split 0..7 (64 k each)
    const int bq = (tid >> 4) & 1;    // 2 groups of 8 batch rows
    const int cq = tid & 15;          // 4 gate cols each
    const int kbeg = ks * 64;
    int hb[8];
#pragma unroll
    for (int r = 0; r < 8; ++r)
        hb[r] = (bq * 8 + r) * SHP + (bq ? 16 : 0);   // +16-word skew kills 8-row conflicts

    // combine mapping: batch row ub, cols c0c..c0c+3 (one gate, 4 units)
    const int c0c = (tid & 15) * 4;
    const size_t Goff_c = (size_t)(c0c >> 4) * Hdim + u0 + (c0c & 15);

    grid_barrier(gen0 + 1);   // publish h(t=-1)=0 chip-wide

    for (int t = 0; t < Tdim; ++t) {
        const float* hrd = (t & 1) ? g_bufB : g_bufA;
        float*       hwr = (t & 1) ? g_bufA : g_bufB;

        // stage h tile (L2-coherent reads), with skew for rows >= 8
        for (int i = tid; i < 16 * 128; i += 256) {
            int bb = i >> 7, kq = i & 127;
            float4 v = __ldcg((const float4*)&hrd[(b0 + bb) * Hdim + kq * 4]);
            *(float4*)&sH[bb * SHP + (bb >= 8 ? 16 : 0) + kq * 4] = v;
        }
        __syncthreads();

        // dot: acc2[8b][4c], each a (even-k, odd-k) partial pair
        ull acc2[8][4];
#pragma unroll
        for (int r = 0; r < 8; ++r)
#pragma unroll
            for (int j = 0; j < 4; ++j) acc2[r][j] = 0ull;

#pragma unroll 4
        for (int k = kbeg; k < kbeg + 64; k += 4) {
            float4 w0 = *(const float4*)&sWt[(k + 0) * 64 + cq * 4];
            float4 w1 = *(const float4*)&sWt[(k + 1) * 64 + cq * 4];
            float4 w2 = *(const float4*)&sWt[(k + 2) * 64 + cq * 4];
            float4 w3 = *(const float4*)&sWt[(k + 3) * 64 + cq * 4];
            ull wp0[4], wp1[4];
            PK2(wp0[0], w0.x, w1.x); PK2(wp0[1], w0.y, w1.y);
            PK2(wp0[2], w0.z, w1.z); PK2(wp0[3], w0.w, w1.w);
            PK2(wp1[0], w2.x, w3.x); PK2(wp1[1], w2.y, w3.y);
            PK2(wp1[2], w2.z, w3.z); PK2(wp1[3], w2.w, w3.w);
#pragma unroll
            for (int r = 0; r < 8; ++r) {
                ulonglong2 hv = *(const ulonglong2*)&sH[hb[r] + k];  // (hk,hk+1),(hk+2,hk+3)
                FMA2(acc2[r][0], hv.x, wp0[0]);
                FMA2(acc2[r][1], hv.x, wp0[1]);
                FMA2(acc2[r][2], hv.x, wp0[2]);
                FMA2(acc2[r][3], hv.x, wp0[3]);
                FMA2(acc2[r][0], hv.y, wp1[0]);
                FMA2(acc2[r][1], hv.y, wp1[1]);
                FMA2(acc2[r][2], hv.y, wp1[2]);
                FMA2(acc2[r][3], hv.y, wp1[3]);
            }
        }
        // fold k-pairs and write partials
#pragma unroll
        for (int r = 0; r < 8; ++r) {
            float lo[4], hi[4];
#pragma unroll
            for (int j = 0; j < 4; ++j) UPK2(lo[j], hi[j], acc2[r][j]);
            float4 o = make_float4(lo[0] + hi[0], lo[1] + hi[1],
                                   lo[2] + hi[2], lo[3] + hi[3]);
            *(float4*)&sRed[ks * 1024 + (bq * 8 + r) * 64 + cq * 4] = o;
        }
        __syncthreads();

        // combine k-split partials + precomputed input gates
        {
            float4 s = *(const float4*)&sRed[0 * 1024 + ub * 64 + c0c];
#pragma unroll
            for (int p = 1; p < 8; ++p) {
                float4 v = *(const float4*)&sRed[p * 1024 + ub * 64 + c0c];
                s.x += v.x; s.y += v.y; s.z += v.z; s.w += v.w;
            }
            float4 Gv = __ldg((const float4*)&g_G[((size_t)gb * Tdim + t) * G4 + Goff_c]);
            s.x += Gv.x; s.y += Gv.y; s.z += Gv.z; s.w += Gv.w;
            *(float4*)&sGate[ub * 68 + c0c] = s;
        }
        __syncthreads();

        // state update (i,f,g,o ordering per jnp.split)
        {
            float gi = sGate[ub * 68 + 0  + lu];
            float gf = sGate[ub * 68 + 16 + lu];
            float gg = sGate[ub * 68 + 32 + lu];
            float go = sGate[ub * 68 + 48 + lu];
            float si = 1.f / (1.f + expf(-gi));
            float sf = 1.f / (1.f + expf(-gf));
            float so = 1.f / (1.f + expf(-go));
            float cn = sf * c_reg + si * tanhf(gg);
            float hn = so * tanhf(cn);
            if (t < len) {
                c_reg = cn; h_reg = hn;
            } else if (layer) {
                c_reg = c0f_r; h_reg = h0f_r;   // layer-1 masked: reset to layer-0 final
            }                                    // layer-0 masked: carry (keep regs)
            hwr[gb * Hdim + gu] = h_reg;
            hs_out[((size_t)gb * Tdim + t) * Hdim + gu] = h_reg;
        }

        grid_barrier(gen0 + 2 + t);
    }

    if (layer == 0) {
        g_h0f[gb * Hdim + gu] = h_reg;
        g_c0f[gb * Hdim + gu] = c_reg;
    }
}

// ---------------- tail: out2 = hs1[b=63] ----------------
__global__ void tail_copy(float* __restrict__ out) {
    size_t i = (size_t)blockIdx.x * 256 + threadIdx.x;   // 65536 float4s
    float4 v = *(const float4*)&out[(size_t)63 * Tdim * Hdim + i * 4];
    *(float4*)&out[(size_t)Bdim * Tdim * Hdim + i * 4] = v;
}

// ---------------- launch ----------------
extern "C" void kernel_launch(void* const* d_in, const int* in_sizes, int n_in,
                              void* d_out, int out_size) {
    const float* x    = (const float*)d_in[0];
    const int*   len  = (const int*)  d_in[1];
    const float* Wih0 = (const float*)d_in[2];
    const float* Whh0 = (const float*)d_in[3];
    const float* bih0 = (const float*)d_in[4];
    const float* bhh0 = (const float*)d_in[5];
    const float* Wih1 = (const float*)d_in[6];
    const float* Whh1 = (const float*)d_in[7];
    const float* bih1 = (const float*)d_in[8];
    const float* bhh1 = (const float*)d_in[9];
    float* out = (float*)d_out;

    constexpr size_t REC_SMEM =
        (512 * 64 + (16 * SHP + 16) + 8 * 16 * 64 + 16 * 68) * sizeof(float);  // 201280 B
    cudaFuncSetAttribute(lstm_rec, cudaFuncAttributeMaxDynamicSharedMemorySize,
                         (int)REC_SMEM);

    void* pG = nullptr;  cudaGetSymbolAddress(&pG,  g_G);
    void* pH0 = nullptr; cudaGetSymbolAddress(&pH0, g_hs0);

    dim3 gemm_grid(G4 / 64, (Bdim * Tdim) / 128);   // (32, 256)

    // Layer 0: input projection then recurrence
    gemm_nt_bias<<<gemm_grid, 256>>>(x, Wih0, bih0, bhh0, (float*)pG, INdim);
    lstm_rec<<<NBLK, 256, REC_SMEM>>>(Whh0, len, (float*)pH0, 0);

    // Layer 1: input projection (from hs0) then recurrence, writes hs1 to out
    gemm_nt_bias<<<gemm_grid, 256>>>((const float*)pH0, Wih1, bih1, bhh1,
                                     (float*)pG, Hdim);
    lstm_rec<<<NBLK, 256, REC_SMEM>>>(Whh1, len, out, 1);

    // output tail = hs1[last batch]
    tail_copy<<<256, 256>>>(out);
}

// round 6
// speedup vs baseline: 1.1061x; 1.1061x over previous
#include <cuda_runtime.h>
#include <math.h>
#include <stdint.h>
#include <stddef.h>

#define Bdim  64
#define Tdim  512
#define INdim 256
#define Hdim  512
#define G4    2048
#define NBLK  128
#define SHP   516     // h tile row pitch (floats): 516*4B -> rows 16 banks apart

typedef unsigned long long ull;

// ---------------- packed f32x2 helpers ----------------
#define PK2(d, lo, hi) \
    asm("mov.b64 %0, {%1, %2};" : "=l"(d) : "f"(lo), "f"(hi))
#define UPK2(lo, hi, v) \
    asm("mov.b64 {%0, %1}, %2;" : "=f"(lo), "=f"(hi) : "l"(v))
#define FMA2(acc, a, b) \
    asm("fma.rn.f32x2 %0, %1, %2, %0;" : "+l"(acc) : "l"(a), "l"(b))

// ---------------- device-global scratch (no allocations allowed) ----------------
__device__ __align__(16) float g_G[(size_t)Bdim * Tdim * G4];     // input-gate precompute
__device__ __align__(16) float g_hs0[(size_t)Bdim * Tdim * Hdim]; // layer-0 hidden sequence
__device__ __align__(16) float g_bufA[Bdim * Hdim];               // double-buffered h state
__device__ __align__(16) float g_bufB[Bdim * Hdim];
__device__ __align__(16) float g_h0f[Bdim * Hdim];                // layer-0 final h
__device__ __align__(16) float g_c0f[Bdim * Hdim];                // layer-0 final c
__device__ unsigned g_arrive[NBLK];                               // per-CTA arrival flags
__device__ volatile unsigned g_release;                           // barrier release word

// ---------------- flag-array grid barrier (all NBLK CTAs resident) ----------------
__device__ __forceinline__ void grid_barrier(unsigned target) {
    __syncthreads();
    const int tid = threadIdx.x;
    if (tid == 0) {
        __threadfence();
        ((volatile unsigned*)g_arrive)[blockIdx.x] = target;
    }
    if (blockIdx.x == 0) {
        if (tid < NBLK) {
            while (((volatile unsigned*)g_arrive)[tid] != target) { }
        }
        __syncthreads();
        if (tid == 0) {
            __threadfence();
            g_release = target;
        }
    } else if (tid == 0) {
        while (g_release != target) { }
    }
    __syncthreads();
}

// ---------------- GEMM: C[m,n] = sum_k A[m,k]*Bw[n,k] + bias1[n] + bias2[n] ----------------
// BM=128, BN=64, BK=16, 256 threads, 8x4 per thread, f32x2 math,
// register-prefetch software pipeline over K tiles.
__global__ __launch_bounds__(256) void gemm_nt_bias(
    const float* __restrict__ A,
    const float* __restrict__ Bw,
    const float* __restrict__ bias1,
    const float* __restrict__ bias2,
    float* __restrict__ C,
    int K)
{
    __shared__ __align__(16) float As[16 * 132];
    __shared__ __align__(16) float Bs[16 * 68];
    const int tid = threadIdx.x;
    const int m0 = blockIdx.y * 128;
    const int n0 = blockIdx.x * 64;
    const int ty = tid >> 4;
    const int tx = tid & 15;

    // staging indices
    const int arow0 = (0 * 256 + tid) >> 2, akq0 = tid & 3;
    const int arow1 = (1 * 256 + tid) >> 2, akq1 = tid & 3;
    const int brow  = tid >> 2,             bkq  = tid & 3;

    ull acc2[4][4];
#pragma unroll
    for (int p = 0; p < 4; ++p)
#pragma unroll
        for (int j = 0; j < 4; ++j) acc2[p][j] = 0ull;

    // prefetch tile 0
    float4 pa0 = __ldg((const float4*)&A[(size_t)(m0 + arow0) * K + akq0 * 4]);
    float4 pa1 = __ldg((const float4*)&A[(size_t)(m0 + arow1) * K + akq1 * 4]);
    float4 pb  = __ldg((const float4*)&Bw[(size_t)(n0 + brow) * K + bkq * 4]);

    for (int k0 = 0; k0 < K; k0 += 16) {
        // store prefetched tile to smem (transposed)
        As[(akq0 * 4 + 0) * 132 + arow0] = pa0.x;
        As[(akq0 * 4 + 1) * 132 + arow0] = pa0.y;
        As[(akq0 * 4 + 2) * 132 + arow0] = pa0.z;
        As[(akq0 * 4 + 3) * 132 + arow0] = pa0.w;
        As[(akq1 * 4 + 0) * 132 + arow1] = pa1.x;
        As[(akq1 * 4 + 1) * 132 + arow1] = pa1.y;
        As[(akq1 * 4 + 2) * 132 + arow1] = pa1.z;
        As[(akq1 * 4 + 3) * 132 + arow1] = pa1.w;
        Bs[(bkq * 4 + 0) * 68 + brow] = pb.x;
        Bs[(bkq * 4 + 1) * 68 + brow] = pb.y;
        Bs[(bkq * 4 + 2) * 68 + brow] = pb.z;
        Bs[(bkq * 4 + 3) * 68 + brow] = pb.w;
        __syncthreads();

        // prefetch next tile (overlaps with compute below)
        if (k0 + 16 < K) {
            int kn = k0 + 16;
            pa0 = __ldg((const float4*)&A[(size_t)(m0 + arow0) * K + kn + akq0 * 4]);
            pa1 = __ldg((const float4*)&A[(size_t)(m0 + arow1) * K + kn + akq1 * 4]);
            pb  = __ldg((const float4*)&Bw[(size_t)(n0 + brow) * K + kn + bkq * 4]);
        }

#pragma unroll
        for (int kk = 0; kk < 16; ++kk) {
            ulonglong2 av0 = *(const ulonglong2*)&As[kk * 132 + ty * 8];
            ulonglong2 av1 = *(const ulonglong2*)&As[kk * 132 + ty * 8 + 4];
            float4 bv = *(const float4*)&Bs[kk * 68 + tx * 4];
            ull bp0, bp1, bp2, bp3;
            PK2(bp0, bv.x, bv.x); PK2(bp1, bv.y, bv.y);
            PK2(bp2, bv.z, bv.z); PK2(bp3, bv.w, bv.w);
            ull ap[4] = {av0.x, av0.y, av1.x, av1.y};
#pragma unroll
            for (int p = 0; p < 4; ++p) {
                FMA2(acc2[p][0], ap[p], bp0);
                FMA2(acc2[p][1], ap[p], bp1);
                FMA2(acc2[p][2], ap[p], bp2);
                FMA2(acc2[p][3], ap[p], bp3);
            }
        }
        __syncthreads();
    }

    float4 b1 = __ldg((const float4*)&bias1[n0 + tx * 4]);
    float4 b2 = __ldg((const float4*)&bias2[n0 + tx * 4]);
    float bs[4] = {b1.x + b2.x, b1.y + b2.y, b1.z + b2.z, b1.w + b2.w};
#pragma unroll
    for (int p = 0; p < 4; ++p) {
        float lo[4], hi[4];
#pragma unroll
        for (int j = 0; j < 4; ++j) UPK2(lo[j], hi[j], acc2[p][j]);
        float4 o0 = make_float4(lo[0] + bs[0], lo[1] + bs[1], lo[2] + bs[2], lo[3] + bs[3]);
        float4 o1 = make_float4(hi[0] + bs[0], hi[1] + bs[1], hi[2] + bs[2], hi[3] + bs[3]);
        *(float4*)&C[(size_t)(m0 + ty * 8 + 2 * p + 0) * G4 + n0 + tx * 4] = o0;
        *(float4*)&C[(size_t)(m0 + ty * 8 + 2 * p + 1) * G4 + n0 + tx * 4] = o1;
    }
}

// ---------------- persistent LSTM recurrence ----------------
// 128 CTAs = 4 batch-tiles x 32 unit-tiles; 512 threads (16 warps).
// W slice stored PAIR-INTERLEAVED in smem: sWtp[kp*128 + c*2 + p] = W[2kp+p][c],
// so FMA2 operands (w even/odd pair, h even/odd pair) come straight from LDS —
// zero mov.b64 packs in the inner loop. Dot mapping: ks(8) x bq(4) x cq(16),
// thread tile 4b x 4cols x (even,odd k-lane), cols {2cq,2cq+1,32+2cq,33+2cq}
// (bank-conflict-free: each warp's 16 LDS.128 tile all 32 banks exactly twice).
__global__ __launch_bounds__(512, 1) void lstm_rec(
    const float* __restrict__ Whh,
    const int*   __restrict__ length,
    float*       __restrict__ hs_out,
    int layer)
{
    extern __shared__ float sm[];
    float* sWtp  = sm;                    // [256 kp][128]
    float* sH    = sWtp + 256 * 128;      // [16][SHP]
    float* sRed  = sH + 16 * SHP;         // [8][16][64]
    float* sGate = sRed + 8 * 16 * 64;    // [16][68]

    const int tid = threadIdx.x;
    const int ui = blockIdx.x & 31, bi = blockIdx.x >> 5;
    const int u0 = ui * 16, b0 = bi * 16;

    const unsigned gen0 = g_release;      // barrier base (replay-safe)

    // Stage W_hh slice pair-interleaved.
    for (int i = tid; i < 64 * 128; i += 512) {
        int c = i & 63;
        int kq = i >> 6;  // 0..127 (4 k each)
        int grow = (c >> 4) * Hdim + u0 + (c & 15);
        float4 v = __ldg((const float4*)&Whh[(size_t)grow * Hdim + kq * 4]);
        int base = (2 * kq) * 128 + 2 * c;
        *(float2*)&sWtp[base]       = make_float2(v.x, v.y);   // k=4kq,4kq+1
        *(float2*)&sWtp[base + 128] = make_float2(v.z, v.w);   // k=4kq+2,4kq+3
    }

    // state-cell mapping (tid < 256): one thread per (batch, unit)
    const int ub = tid >> 4, lu = tid & 15;
    const int gb = b0 + (ub & 15);
    const int gu = u0 + lu;
    int   len = 0;
    float h0f_r = 0.f, c0f_r = 0.f;
    float h_reg = 0.f, c_reg = 0.f;
    if (tid < 256) {
        len = __ldg(&length[gb]);
        if (layer) {
            h0f_r = g_h0f[gb * Hdim + gu];
            c0f_r = g_c0f[gb * Hdim + gu];
        }
        g_bufA[gb * Hdim + gu] = 0.f;   // h(t=-1) = 0
    }

    // dot-phase mapping: tid = ks*64 + bq*16 + cq
    const int ks = tid >> 6;          // 0..7, 64 k each (warp-uniform)
    const int bq = (tid >> 4) & 3;    // 4 batch rows each
    const int cq = tid & 15;
    const int kbeg = ks * 64;
    int hrow[4];
#pragma unroll
    for (int r = 0; r < 4; ++r) hrow[r] = (bq * 4 + r) * SHP;

    // combine mapping (tid < 256)
    const int c0c = (tid & 15) * 4;
    const size_t Goff_c = (size_t)(c0c >> 4) * Hdim + u0 + (c0c & 15);

    grid_barrier(gen0 + 1);   // publish h(t=-1)=0 chip-wide

    for (int t = 0; t < Tdim; ++t) {
        const float* hrd = (t & 1) ? g_bufB : g_bufA;
        float*       hwr = (t & 1) ? g_bufA : g_bufB;

        // prefetch this step's input-gate block (hidden behind the dot phase)
        float4 Gv = make_float4(0.f, 0.f, 0.f, 0.f);
        if (tid < 256)
            Gv = __ldg((const float4*)&g_G[((size_t)gb * Tdim + t) * G4 + Goff_c]);

        // stage h tile
        for (int i = tid; i < 16 * 128; i += 512) {
            int bb = i >> 7, kq = i & 127;
            float4 v = __ldcg((const float4*)&hrd[(b0 + bb) * Hdim + kq * 4]);
            *(float4*)&sH[bb * SHP + kq * 4] = v;
        }
        __syncthreads();

        // dot: acc2[4 rows][4 cols], each ull = (even-k, odd-k) partial pair
        ull acc2[4][4];
#pragma unroll
        for (int r = 0; r < 4; ++r)
#pragma unroll
            for (int j = 0; j < 4; ++j) acc2[r][j] = 0ull;

#pragma unroll 4
        for (int k = kbeg; k < kbeg + 64; k += 4) {
            const int kp = k >> 1;
            const float* wp = &sWtp[kp * 128 + cq * 4];
            ulonglong2 wA0 = *(const ulonglong2*)wp;          // kp:   cols 2cq, 2cq+1
            ulonglong2 wB0 = *(const ulonglong2*)(wp + 64);   // kp:   cols 32+2cq, 33+2cq
            ulonglong2 wA1 = *(const ulonglong2*)(wp + 128);  // kp+1: cols 2cq, 2cq+1
            ulonglong2 wB1 = *(const ulonglong2*)(wp + 192);  // kp+1: cols 32+2cq, 33+2cq
#pragma unroll
            for (int r = 0; r < 4; ++r) {
                ulonglong2 hv = *(const ulonglong2*)&sH[hrow[r] + k]; // (k,k+1),(k+2,k+3)
                FMA2(acc2[r][0], hv.x, wA0.x);
                FMA2(acc2[r][1], hv.x, wA0.y);
                FMA2(acc2[r][2], hv.x, wB0.x);
                FMA2(acc2[r][3], hv.x, wB0.y);
                FMA2(acc2[r][0], hv.y, wA1.x);
                FMA2(acc2[r][1], hv.y, wA1.y);
                FMA2(acc2[r][2], hv.y, wB1.x);
                FMA2(acc2[r][3], hv.y, wB1.y);
            }
        }
        // fold even/odd lanes; write partials (cols 2cq,2cq+1 and 32+2cq,33+2cq)
#pragma unroll
        for (int r = 0; r < 4; ++r) {
            float lo, hi, s0, s1, s2, s3;
            UPK2(lo, hi, acc2[r][0]); s0 = lo + hi;
            UPK2(lo, hi, acc2[r][1]); s1 = lo + hi;
            UPK2(lo, hi, acc2[r][2]); s2 = lo + hi;
            UPK2(lo, hi, acc2[r][3]); s3 = lo + hi;
            int rowoff = ks * 1024 + (bq * 4 + r) * 64;
            *(float2*)&sRed[rowoff + 2 * cq]      = make_float2(s0, s1);
            *(float2*)&sRed[rowoff + 32 + 2 * cq] = make_float2(s2, s3);
        }
        __syncthreads();

        // combine k-split partials + prefetched input gates
        if (tid < 256) {
            float4 s = *(const float4*)&sRed[0 * 1024 + ub * 64 + c0c];
#pragma unroll
            for (int p = 1; p < 8; ++p) {
                float4 v = *(const float4*)&sRed[p * 1024 + ub * 64 + c0c];
                s.x += v.x; s.y += v.y; s.z += v.z; s.w += v.w;
            }
            s.x += Gv.x; s.y += Gv.y; s.z += Gv.z; s.w += Gv.w;
            *(float4*)&sGate[ub * 68 + c0c] = s;
        }
        __syncthreads();

        // state update (i,f,g,o per jnp.split)
        if (tid < 256) {
            float gi = sGate[ub * 68 + 0  + lu];
            float gf = sGate[ub * 68 + 16 + lu];
            float gg = sGate[ub * 68 + 32 + lu];
            float go = sGate[ub * 68 + 48 + lu];
            float si = 1.f / (1.f + expf(-gi));
            float sf = 1.f / (1.f + expf(-gf));
            float so = 1.f / (1.f + expf(-go));
            float cn = sf * c_reg + si * tanhf(gg);
            float hn = so * tanhf(cn);
            if (t < len) {
                c_reg = cn; h_reg = hn;
            } else if (layer) {
                c_reg = c0f_r; h_reg = h0f_r;   // layer-1 masked: reset to layer-0 final
            }                                    // layer-0 masked: carry
            hwr[gb * Hdim + gu] = h_reg;
            hs_out[((size_t)gb * Tdim + t) * Hdim + gu] = h_reg;
        }

        grid_barrier(gen0 + 2 + t);
    }

    if (layer == 0 && tid < 256) {
        g_h0f[gb * Hdim + gu] = h_reg;
        g_c0f[gb * Hdim + gu] = c_reg;
    }
}

// ---------------- tail: out2 = hs1[b=63] ----------------
__global__ void tail_copy(float* __restrict__ out) {
    size_t i = (size_t)blockIdx.x * 256 + threadIdx.x;   // 65536 float4s
    float4 v = *(const float4*)&out[(size_t)63 * Tdim * Hdim + i * 4];
    *(float4*)&out[(size_t)Bdim * Tdim * Hdim + i * 4] = v;
}

// ---------------- launch ----------------
extern "C" void kernel_launch(void* const* d_in, const int* in_sizes, int n_in,
                              void* d_out, int out_size) {
    const float* x    = (const float*)d_in[0];
    const int*   len  = (const int*)  d_in[1];
    const float* Wih0 = (const float*)d_in[2];
    const float* Whh0 = (const float*)d_in[3];
    const float* bih0 = (const float*)d_in[4];
    const float* bhh0 = (const float*)d_in[5];
    const float* Wih1 = (const float*)d_in[6];
    const float* Whh1 = (const float*)d_in[7];
    const float* bih1 = (const float*)d_in[8];
    const float* bhh1 = (const float*)d_in[9];
    float* out = (float*)d_out;

    constexpr size_t REC_SMEM =
        (256 * 128 + 16 * SHP + 8 * 16 * 64 + 16 * 68) * sizeof(float);  // 201216 B
    cudaFuncSetAttribute(lstm_rec, cudaFuncAttributeMaxDynamicSharedMemorySize,
                         (int)REC_SMEM);

    void* pG = nullptr;  cudaGetSymbolAddress(&pG,  g_G);
    void* pH0 = nullptr; cudaGetSymbolAddress(&pH0, g_hs0);

    dim3 gemm_grid(G4 / 64, (Bdim * Tdim) / 128);   // (32, 256)

    // Layer 0
    gemm_nt_bias<<<gemm_grid, 256>>>(x, Wih0, bih0, bhh0, (float*)pG, INdim);
    lstm_rec<<<NBLK, 512, REC_SMEM>>>(Whh0, len, (float*)pH0, 0);

    // Layer 1
    gemm_nt_bias<<<gemm_grid, 256>>>((const float*)pH0, Wih1, bih1, bhh1,
                                     (float*)pG, Hdim);
    lstm_rec<<<NBLK, 512, REC_SMEM>>>(Whh1, len, out, 1);

    // output tail = hs1[last batch]
    tail_copy<<<256, 256>>>(out);
}

// round 8
// speedup vs baseline: 1.2959x; 1.1716x over previous
#include <cuda_runtime.h>
#include <math.h>
#include <stdint.h>
#include <stddef.h>

#define Bdim  64
#define Tdim  512
#define INdim 256
#define Hdim  512
#define G4    2048
#define NBLK  128
#define SHP   516     // h tile row pitch (floats)

typedef unsigned long long ull;

// ---------------- packed f32x2 helpers ----------------
#define PK2(d, lo, hi) \
    asm("mov.b64 %0, {%1, %2};" : "=l"(d) : "f"(lo), "f"(hi))
#define UPK2(lo, hi, v) \
    asm("mov.b64 {%0, %1}, %2;" : "=f"(lo), "=f"(hi) : "l"(v))
#define FMA2(acc, a, b) \
    asm("fma.rn.f32x2 %0, %1, %2, %0;" : "+l"(acc) : "l"(a), "l"(b))

// ---------------- device-global scratch ----------------
__device__ __align__(16) float g_G[(size_t)Bdim * Tdim * G4];
__device__ __align__(16) float g_hs0[(size_t)Bdim * Tdim * Hdim];
__device__ __align__(16) float g_bufA[Bdim * Hdim];
__device__ __align__(16) float g_bufB[Bdim * Hdim];
__device__ __align__(16) float g_h0f[Bdim * Hdim];
__device__ __align__(16) float g_c0f[Bdim * Hdim];
__device__ unsigned g_arrive[NBLK];           // per-CTA arrival flags
__device__ volatile unsigned g_rel[4];        // per-batch-group release words

// ---------------- per-group barrier (32 CTAs per batch group) ----------------
__device__ __forceinline__ void group_barrier(int grp, int ui, unsigned target) {
    __syncthreads();
    const int tid = threadIdx.x;
    if (tid == 0) {
        __threadfence();
        ((volatile unsigned*)g_arrive)[blockIdx.x] = target;
    }
    if (ui == 0) {
        if (tid < 32) {
            while (((volatile unsigned*)g_arrive)[grp * 32 + tid] != target) { }
        }
        __syncthreads();
        if (tid == 0) {
            __threadfence();
            g_rel[grp] = target;
        }
    } else if (tid == 0) {
        while (g_rel[grp] != target) { }
    }
    __syncthreads();
}

// ---------------- GEMM: C[m,n] = sum_k A[m,k]*Bw[n,k] + bias1[n]+bias2[n] ----------------
// BM=128, BN=128, BK=16, 256 threads, 8x8 per thread, f32x2, reg-prefetch pipeline.
// Skips m-blocks whose 128 rows are entirely masked (t0 >= len[b]); those gate
// rows are never consumed by the recurrence.
__global__ __launch_bounds__(256, 2) void gemm_nt_bias(
    const float* __restrict__ A,
    const float* __restrict__ Bw,
    const float* __restrict__ bias1,
    const float* __restrict__ bias2,
    const int*   __restrict__ length,
    float* __restrict__ C,
    int K)
{
    const int m0 = blockIdx.y * 128;
    const int n0 = blockIdx.x * 128;
    {   // m-block lies inside one batch element: b = m0/512, t0 = m0%512
        const int b = m0 >> 9, t0 = m0 & 511;
        if (__ldg(&length[b]) <= t0) return;   // fully masked -> gates unused
    }

    __shared__ __align__(16) float As[16 * 132];
    __shared__ __align__(16) float Bs[16 * 132];
    const int tid = threadIdx.x;
    const int ty = tid >> 4;   // 8-row group
    const int tx = tid & 15;   // 8-col group

    const int row0 = tid >> 2, row1 = (256 + tid) >> 2, kq = tid & 3;

    ull acc2[4][8];
#pragma unroll
    for (int p = 0; p < 4; ++p)
#pragma unroll
        for (int j = 0; j < 8; ++j) acc2[p][j] = 0ull;

    // prefetch tile 0
    float4 pa0 = __ldg((const float4*)&A[(size_t)(m0 + row0) * K + kq * 4]);
    float4 pa1 = __ldg((const float4*)&A[(size_t)(m0 + row1) * K + kq * 4]);
    float4 pb0 = __ldg((const float4*)&Bw[(size_t)(n0 + row0) * K + kq * 4]);
    float4 pb1 = __ldg((const float4*)&Bw[(size_t)(n0 + row1) * K + kq * 4]);

    for (int k0 = 0; k0 < K; k0 += 16) {
        As[(kq * 4 + 0) * 132 + row0] = pa0.x;
        As[(kq * 4 + 1) * 132 + row0] = pa0.y;
        As[(kq * 4 + 2) * 132 + row0] = pa0.z;
        As[(kq * 4 + 3) * 132 + row0] = pa0.w;
        As[(kq * 4 + 0) * 132 + row1] = pa1.x;
        As[(kq * 4 + 1) * 132 + row1] = pa1.y;
        As[(kq * 4 + 2) * 132 + row1] = pa1.z;
        As[(kq * 4 + 3) * 132 + row1] = pa1.w;
        Bs[(kq * 4 + 0) * 132 + row0] = pb0.x;
        Bs[(kq * 4 + 1) * 132 + row0] = pb0.y;
        Bs[(kq * 4 + 2) * 132 + row0] = pb0.z;
        Bs[(kq * 4 + 3) * 132 + row0] = pb0.w;
        Bs[(kq * 4 + 0) * 132 + row1] = pb1.x;
        Bs[(kq * 4 + 1) * 132 + row1] = pb1.y;
        Bs[(kq * 4 + 2) * 132 + row1] = pb1.z;
        Bs[(kq * 4 + 3) * 132 + row1] = pb1.w;
        __syncthreads();

        if (k0 + 16 < K) {   // prefetch next tile (overlaps compute)
            int kn = k0 + 16;
            pa0 = __ldg((const float4*)&A[(size_t)(m0 + row0) * K + kn + kq * 4]);
            pa1 = __ldg((const float4*)&A[(size_t)(m0 + row1) * K + kn + kq * 4]);
            pb0 = __ldg((const float4*)&Bw[(size_t)(n0 + row0) * K + kn + kq * 4]);
            pb1 = __ldg((const float4*)&Bw[(size_t)(n0 + row1) * K + kn + kq * 4]);
        }

#pragma unroll
        for (int kk = 0; kk < 16; ++kk) {
            ulonglong2 av0 = *(const ulonglong2*)&As[kk * 132 + ty * 8];
            ulonglong2 av1 = *(const ulonglong2*)&As[kk * 132 + ty * 8 + 4];
            float4 bv0 = *(const float4*)&Bs[kk * 132 + tx * 8];
            float4 bv1 = *(const float4*)&Bs[kk * 132 + tx * 8 + 4];
            ull ap[4] = {av0.x, av0.y, av1.x, av1.y};
            ull bp[8];
            PK2(bp[0], bv0.x, bv0.x); PK2(bp[1], bv0.y, bv0.y);
            PK2(bp[2], bv0.z, bv0.z); PK2(bp[3], bv0.w, bv0.w);
            PK2(bp[4], bv1.x, bv1.x); PK2(bp[5], bv1.y, bv1.y);
            PK2(bp[6], bv1.z, bv1.z); PK2(bp[7], bv1.w, bv1.w);
#pragma unroll
            for (int p = 0; p < 4; ++p)
#pragma unroll
                for (int j = 0; j < 8; ++j)
                    FMA2(acc2[p][j], ap[p], bp[j]);
        }
        __syncthreads();
    }

    float4 c1a = __ldg((const float4*)&bias1[n0 + tx * 8]);
    float4 c1b = __ldg((const float4*)&bias1[n0 + tx * 8 + 4]);
    float4 c2a = __ldg((const float4*)&bias2[n0 + tx * 8]);
    float4 c2b = __ldg((const float4*)&bias2[n0 + tx * 8 + 4]);
    float bs[8] = {c1a.x + c2a.x, c1a.y + c2a.y, c1a.z + c2a.z, c1a.w + c2a.w,
                   c1b.x + c2b.x, c1b.y + c2b.y, c1b.z + c2b.z, c1b.w + c2b.w};
#pragma unroll
    for (int p = 0; p < 4; ++p) {
        float lo[8], hi[8];
#pragma unroll
        for (int j = 0; j < 8; ++j) UPK2(lo[j], hi[j], acc2[p][j]);
        size_t r0 = (size_t)(m0 + ty * 8 + 2 * p + 0) * G4 + n0 + tx * 8;
        size_t r1 = (size_t)(m0 + ty * 8 + 2 * p + 1) * G4 + n0 + tx * 8;
        *(float4*)&C[r0]     = make_float4(lo[0] + bs[0], lo[1] + bs[1], lo[2] + bs[2], lo[3] + bs[3]);
        *(float4*)&C[r0 + 4] = make_float4(lo[4] + bs[4], lo[5] + bs[5], lo[6] + bs[6], lo[7] + bs[7]);
        *(float4*)&C[r1]     = make_float4(hi[0] + bs[0], hi[1] + bs[1], hi[2] + bs[2], hi[3] + bs[3]);
        *(float4*)&C[r1 + 4] = make_float4(hi[4] + bs[4], hi[5] + bs[5], hi[6] + bs[6], hi[7] + bs[7]);
    }
}

// ---------------- persistent LSTM recurrence ----------------
// 128 CTAs = 4 batch-groups x 32 unit-tiles; 512 threads. Batch groups are
// fully independent -> per-group barrier + early exit at the group's max length.
__global__ __launch_bounds__(512, 1) void lstm_rec(
    const float* __restrict__ Whh,
    const int*   __restrict__ length,
    float*       __restrict__ hs_out,
    int layer)
{
    extern __shared__ float sm[];
    float* sWtp  = sm;                    // [256 kp][128] pair-interleaved W
    float* sH    = sWtp + 256 * 128;      // [16][SHP]
    float* sRed  = sH + 16 * SHP;         // [8][16][64]
    float* sGate = sRed + 8 * 16 * 64;    // [16][68]
    __shared__ int sLen[16];

    const int tid = threadIdx.x;
    const int ui = blockIdx.x & 31, bi = blockIdx.x >> 5;
    const int u0 = ui * 16, b0 = bi * 16;

    const unsigned gen0 = g_rel[bi];      // barrier base (replay-safe)

    // Stage W_hh slice pair-interleaved: sWtp[kp*128 + 2c + p] = W[2kp+p][c].
    for (int i = tid; i < 64 * 128; i += 512) {
        int c = i & 63;
        int kq = i >> 6;
        int grow = (c >> 4) * Hdim + u0 + (c & 15);
        float4 v = __ldg((const float4*)&Whh[(size_t)grow * Hdim + kq * 4]);
        int base = (2 * kq) * 128 + 2 * c;
        *(float2*)&sWtp[base]       = make_float2(v.x, v.y);
        *(float2*)&sWtp[base + 128] = make_float2(v.z, v.w);
    }
    if (tid < 16) sLen[tid] = __ldg(&length[b0 + tid]);

    // state-cell mapping (tid < 256)
    const int ub = tid >> 4, lu = tid & 15;
    const int gb = b0 + (ub & 15);
    const int gu = u0 + lu;
    int   len = 0;
    float h0f_r = 0.f, c0f_r = 0.f;
    float h_reg = 0.f, c_reg = 0.f;
    if (tid < 256) {
        len = __ldg(&length[gb]);
        if (layer) {
            h0f_r = g_h0f[gb * Hdim + gu];
            c0f_r = g_c0f[gb * Hdim + gu];
        }
        g_bufA[gb * Hdim + gu] = 0.f;
    }
    __syncthreads();
    int maxlen = 1;
#pragma unroll
    for (int i = 0; i < 16; ++i) maxlen = max(maxlen, sLen[i]);

    // dot-phase mapping: tid = ks*64 + bq*16 + cq
    const int ks = tid >> 6;
    const int bq = (tid >> 4) & 3;
    const int cq = tid & 15;
    const int kbeg = ks * 64;
    int hrow[4];
#pragma unroll
    for (int r = 0; r < 4; ++r) hrow[r] = (bq * 4 + r) * SHP;

    const int c0c = (tid & 15) * 4;
    const size_t Goff_c = (size_t)(c0c >> 4) * Hdim + u0 + (c0c & 15);

    group_barrier(bi, ui, gen0 + 1);   // publish h(t=-1)=0 within group

    for (int t = 0; t < maxlen; ++t) {
        const float* hrd = (t & 1) ? g_bufB : g_bufA;
        float*       hwr = (t & 1) ? g_bufA : g_bufB;

        float4 Gv = make_float4(0.f, 0.f, 0.f, 0.f);
        if (tid < 256)
            Gv = __ldg((const float4*)&g_G[((size_t)gb * Tdim + t) * G4 + Goff_c]);

        for (int i = tid; i < 16 * 128; i += 512) {
            int bb = i >> 7, kq = i & 127;
            float4 v = __ldcg((const float4*)&hrd[(b0 + bb) * Hdim + kq * 4]);
            *(float4*)&sH[bb * SHP + kq * 4] = v;
        }
        __syncthreads();

        ull acc2[4][4];
#pragma unroll
        for (int r = 0; r < 4; ++r)
#pragma unroll
            for (int j = 0; j < 4; ++j) acc2[r][j] = 0ull;

#pragma unroll 4
        for (int k = kbeg; k < kbeg + 64; k += 4) {
            const int kp = k >> 1;
            const float* wp = &sWtp[kp * 128 + cq * 4];
            ulonglong2 wA0 = *(const ulonglong2*)wp;
            ulonglong2 wB0 = *(const ulonglong2*)(wp + 64);
            ulonglong2 wA1 = *(const ulonglong2*)(wp + 128);
            ulonglong2 wB1 = *(const ulonglong2*)(wp + 192);
#pragma unroll
            for (int r = 0; r < 4; ++r) {
                ulonglong2 hv = *(const ulonglong2*)&sH[hrow[r] + k];
                FMA2(acc2[r][0], hv.x, wA0.x);
                FMA2(acc2[r][1], hv.x, wA0.y);
                FMA2(acc2[r][2], hv.x, wB0.x);
                FMA2(acc2[r][3], hv.x, wB0.y);
                FMA2(acc2[r][0], hv.y, wA1.x);
                FMA2(acc2[r][1], hv.y, wA1.y);
                FMA2(acc2[r][2], hv.y, wB1.x);
                FMA2(acc2[r][3], hv.y, wB1.y);
            }
        }
#pragma unroll
        for (int r = 0; r < 4; ++r) {
            float lo, hi, s0, s1, s2, s3;
            UPK2(lo, hi, acc2[r][0]); s0 = lo + hi;
            UPK2(lo, hi, acc2[r][1]); s1 = lo + hi;
            UPK2(lo, hi, acc2[r][2]); s2 = lo + hi;
            UPK2(lo, hi, acc2[r][3]); s3 = lo + hi;
            int rowoff = ks * 1024 + (bq * 4 + r) * 64;
            *(float2*)&sRed[rowoff + 2 * cq]      = make_float2(s0, s1);
            *(float2*)&sRed[rowoff + 32 + 2 * cq] = make_float2(s2, s3);
        }
        __syncthreads();

        if (tid < 256) {
            float4 s = *(const float4*)&sRed[0 * 1024 + ub * 64 + c0c];
#pragma unroll
            for (int p = 1; p < 8; ++p) {
                float4 v = *(const float4*)&sRed[p * 1024 + ub * 64 + c0c];
                s.x += v.x; s.y += v.y; s.z += v.z; s.w += v.w;
            }
            s.x += Gv.x; s.y += Gv.y; s.z += Gv.z; s.w += Gv.w;
            *(float4*)&sGate[ub * 68 + c0c] = s;
        }
        __syncthreads();

        if (tid < 256) {
            float gi = sGate[ub * 68 + 0  + lu];
            float gf = sGate[ub * 68 + 16 + lu];
            float gg = sGate[ub * 68 + 32 + lu];
            float go = sGate[ub * 68 + 48 + lu];
            float si = 1.f / (1.f + expf(-gi));
            float sf = 1.f / (1.f + expf(-gf));
            float so = 1.f / (1.f + expf(-go));
            float cn = sf * c_reg + si * tanhf(gg);
            float hn = so * tanhf(cn);
            if (t < len) {
                c_reg = cn; h_reg = hn;
            } else if (layer) {
                c_reg = c0f_r; h_reg = h0f_r;   // layer-1 masked: reset to layer-0 final
            }                                    // layer-0 masked: carry
            hwr[gb * Hdim + gu] = h_reg;
            hs_out[((size_t)gb * Tdim + t) * Hdim + gu] = h_reg;
        }

        group_barrier(bi, ui, gen0 + 2 + t);
    }

    // t >= maxlen: all batches in this group masked.
    // Layer 0 (carry): tail value is the frozen h_reg.
    // Layer 1 (reset): tail value is h0f (layer-0 final) -- NOT h_reg, which for
    // the group's max-length batch still holds its last real hidden state.
    if (tid < 256) {
        const float h_tail = layer ? h0f_r : h_reg;
        for (int t = maxlen; t < Tdim; ++t)
            hs_out[((size_t)gb * Tdim + t) * Hdim + gu] = h_tail;
        if (layer == 0) {
            g_h0f[gb * Hdim + gu] = h_reg;
            g_c0f[gb * Hdim + gu] = c_reg;
        }
    }
}

// ---------------- tail: out2 = hs1[b=63] ----------------
__global__ void tail_copy(float* __restrict__ out) {
    size_t i = (size_t)blockIdx.x * 256 + threadIdx.x;   // 65536 float4s
    float4 v = *(const float4*)&out[(size_t)63 * Tdim * Hdim + i * 4];
    *(float4*)&out[(size_t)Bdim * Tdim * Hdim + i * 4] = v;
}

// ---------------- launch ----------------
extern "C" void kernel_launch(void* const* d_in, const int* in_sizes, int n_in,
                              void* d_out, int out_size) {
    const float* x    = (const float*)d_in[0];
    const int*   len  = (const int*)  d_in[1];
    const float* Wih0 = (const float*)d_in[2];
    const float* Whh0 = (const float*)d_in[3];
    const float* bih0 = (const float*)d_in[4];
    const float* bhh0 = (const float*)d_in[5];
    const float* Wih1 = (const float*)d_in[6];
    const float* Whh1 = (const float*)d_in[7];
    const float* bih1 = (const float*)d_in[8];
    const float* bhh1 = (const float*)d_in[9];
    float* out = (float*)d_out;

    constexpr size_t REC_SMEM =
        (256 * 128 + 16 * SHP + 8 * 16 * 64 + 16 * 68) * sizeof(float);  // 201216 B
    cudaFuncSetAttribute(lstm_rec, cudaFuncAttributeMaxDynamicSharedMemorySize,
                         (int)REC_SMEM);

    void* pG = nullptr;  cudaGetSymbolAddress(&pG,  g_G);
    void* pH0 = nullptr; cudaGetSymbolAddress(&pH0, g_hs0);

    dim3 gemm_grid(G4 / 128, (Bdim * Tdim) / 128);   // (16, 256)

    // Layer 0
    gemm_nt_bias<<<gemm_grid, 256>>>(x, Wih0, bih0, bhh0, len, (float*)pG, INdim);
    lstm_rec<<<NBLK, 512, REC_SMEM>>>(Whh0, len, (float*)pH0, 0);

    // Layer 1
    gemm_nt_bias<<<gemm_grid, 256>>>((const float*)pH0, Wih1, bih1, bhh1, len,
                                     (float*)pG, Hdim);
    lstm_rec<<<NBLK, 512, REC_SMEM>>>(Whh1, len, out, 1);

    // output tail = hs1[last batch]
    tail_copy<<<256, 256>>>(out);
}